// round 16
// baseline (speedup 1.0000x reference)
#include <cuda_runtime.h>
#include <cuda_bf16.h>
#include <cstdint>

// ---------------- problem constants ----------------
static constexpr int N_SPK = 1024;
static constexpr int N_UTT = 20;
static constexpr int D_EMB = 512;
static constexpr int R_TOT = N_SPK * N_UTT;   // 20480 rows

static constexpr float COS_EPS = 1e-8f;
static constexpr float SIM_EPS = 1e-6f;

// ---------------- GEMM tiling (R8/R15 proven config) ----------------
static constexpr int BM  = 128;               // rows per CTA
static constexpr int BN  = 128;               // centroid cols per CTA
static constexpr int KC  = 64;                // K chunk (bf16) -> 128B rows in smem
static constexpr int NCH = D_EMB / KC;        // 8 chunks
static constexpr int MTILES = R_TOT / BM;     // 160
static constexpr int NTILES = N_SPK / BN;     // 8
static constexpr int NPART  = NTILES * 2;     // 16 row-sum partial arrays
static constexpr int FIN_BLOCKS = 40;

// 3-stage ring: [A_s 16K | B_s 16K] x 3
static constexpr int STAGE_BYTES = 2 * BM * KC * 2;     // 32768
static constexpr int SMEM_DYN = 3 * STAGE_BYTES;        // 98304

// ---------------- scratch (device globals; no allocs allowed) ----------------
__device__ __nv_bfloat16 g_E[R_TOT * D_EMB];      // normalized embeddings (bf16)
__device__ __nv_bfloat16 g_C[N_SPK * D_EMB];      // normalized centroids (bf16)
__device__ float         g_S[N_SPK * D_EMB];      // per-speaker dim sums (fp32)
__device__ float         g_SS[N_SPK];             // ||S||^2 per speaker
__device__ float         g_diag[R_TOT];           // leave-one-out cosine (fp32)
__device__ float         g_rowsum[NPART][R_TOT];  // partial exp sums
__device__ float         g_bsum[FIN_BLOCKS];      // finalize partials
__device__ unsigned int  g_fin;                   // finalize ticket (self-resetting)

// ---------------- PTX helpers (plain-sm_103-safe) ----------------
__device__ __forceinline__ uint32_t smem_u32(const void* p) {
    uint32_t a;
    asm("{ .reg .u64 t; cvta.to.shared.u64 t, %1; cvt.u32.u64 %0, t; }"
        : "=r"(a) : "l"(p));
    return a;
}
__device__ __forceinline__ void cp16(uint32_t dst, const void* src) {
    asm volatile("cp.async.cg.shared.global [%0], [%1], 16;"
                 :: "r"(dst), "l"(src));
}
#define CP_COMMIT() asm volatile("cp.async.commit_group;" ::: "memory")
#define CP_WAIT(n)  asm volatile("cp.async.wait_group %0;" :: "n"(n) : "memory")

#define LDSM_X4(r0, r1, r2, r3, addr)                                          \
    asm volatile("ldmatrix.sync.aligned.m8n8.x4.shared.b16 {%0,%1,%2,%3}, [%4];" \
                 : "=r"(r0), "=r"(r1), "=r"(r2), "=r"(r3) : "r"(addr))

__device__ __forceinline__ void mma16816(float* c, const uint32_t* a,
                                         uint32_t b0, uint32_t b1) {
    asm volatile(
        "mma.sync.aligned.m16n8k16.row.col.f32.bf16.bf16.f32 "
        "{%0,%1,%2,%3}, {%4,%5,%6,%7}, {%8,%9}, {%0,%1,%2,%3};"
        : "+f"(c[0]), "+f"(c[1]), "+f"(c[2]), "+f"(c[3])
        : "r"(a[0]), "r"(a[1]), "r"(a[2]), "r"(a[3]), "r"(b0), "r"(b1));
}

// pack 4 floats (scaled) into 4 bf16 = uint2
__device__ __forceinline__ uint2 pack_bf16x4(float4 v, float scale) {
    __nv_bfloat162 lo, hi;
    lo.x = __float2bfloat16(v.x * scale);
    lo.y = __float2bfloat16(v.y * scale);
    hi.x = __float2bfloat16(v.z * scale);
    hi.y = __float2bfloat16(v.w * scale);
    uint2 pk;
    pk.x = *reinterpret_cast<uint32_t*>(&lo);
    pk.y = *reinterpret_cast<uint32_t*>(&hi);
    return pk;
}

// ============================================================================
// Kernel 1a: per-speaker sums. One block (256 thr) per speaker.
// Streams 20 rows, writes g_S (fp32), g_SS, and the normalized centroid
// directly from registers. Block exits immediately after -> DRAM stays busy.
// ============================================================================
__global__ void __launch_bounds__(256) sum_kernel(const float* __restrict__ emb) {
    __shared__ float sRed[8];
    __shared__ float sCS;

    const int n    = blockIdx.x;
    const int tid  = threadIdx.x;
    const int wid  = tid >> 5;
    const int lane = tid & 31;
    const float* spk = emb + (size_t)n * N_UTT * D_EMB;

    float2 s = {0.f, 0.f};
    #pragma unroll
    for (int m = 0; m < N_UTT; m++) {
        float2 v = *reinterpret_cast<const float2*>(spk + m * D_EMB + 2 * tid);
        s.x += v.x; s.y += v.y;
    }
    *reinterpret_cast<float2*>(&g_S[(size_t)n * D_EMB + 2 * tid]) = s;

    float ssp = s.x * s.x + s.y * s.y;
    #pragma unroll
    for (int o = 16; o > 0; o >>= 1)
        ssp += __shfl_xor_sync(0xFFFFFFFFu, ssp, o);
    if (lane == 0) sRed[wid] = ssp;
    __syncthreads();
    if (tid == 0) {
        float SS = 0.f;
        #pragma unroll
        for (int w = 0; w < 8; w++) SS += sRed[w];
        g_SS[n] = SS;
        float cnorm = sqrtf(SS) * (1.0f / N_UTT);
        sCS = 1.0f / (N_UTT * fmaxf(cnorm, COS_EPS));
    }
    __syncthreads();

    // normalized centroid straight from registers
    {
        const float cs = sCS;
        __nv_bfloat162 o2;
        o2.x = __float2bfloat16(s.x * cs);
        o2.y = __float2bfloat16(s.y * cs);
        *reinterpret_cast<__nv_bfloat162*>(&g_C[(size_t)n * D_EMB + 2 * tid]) = o2;
    }
}

// ============================================================================
// Kernel 1b: warp-per-utterance normalize. grid = 2560 x 256 (8 warps),
// ZERO block barriers. Re-reads the utterance row (L2-resident after 1a),
// reads its speaker's g_S row, algebraic leave-one-out:
//   ec = (se - ee)/(M-1),   cc = (SS - 2 se + ee)/(M-1)^2.
// ============================================================================
__global__ void __launch_bounds__(256) norm_kernel(const float* __restrict__ emb) {
    const int u    = blockIdx.x * 8 + (threadIdx.x >> 5);   // global row 0..20479
    const int lane = threadIdx.x & 31;
    const int n    = u / N_UTT;
    const float invM1 = 1.0f / (N_UTT - 1);

    const float* erow = emb + (size_t)u * D_EMB;
    const float* Srow = g_S + (size_t)n * D_EMB;

    float4 ev[4];
    float ee = 0.f, se = 0.f;
    #pragma unroll
    for (int i = 0; i < 4; i++) {
        int d = lane * 4 + i * 128;
        ev[i] = *reinterpret_cast<const float4*>(erow + d);
        float4 S4 = *reinterpret_cast<const float4*>(Srow + d);
        ee += ev[i].x * ev[i].x + ev[i].y * ev[i].y +
              ev[i].z * ev[i].z + ev[i].w * ev[i].w;
        se += ev[i].x * S4.x + ev[i].y * S4.y +
              ev[i].z * S4.z + ev[i].w * S4.w;
    }
    #pragma unroll
    for (int o = 16; o > 0; o >>= 1) {
        ee += __shfl_xor_sync(0xFFFFFFFFu, ee, o);
        se += __shfl_xor_sync(0xFFFFFFFFu, se, o);
    }

    const float SS = g_SS[n];
    float ec = (se - ee) * invM1;
    float cc = (SS - 2.f * se + ee) * invM1 * invM1;
    float inv_e = 1.0f / fmaxf(sqrtf(ee), COS_EPS);
    float inv_c = 1.0f / fmaxf(sqrtf(cc), COS_EPS);
    if (lane == 0) g_diag[u] = ec * inv_e * inv_c;

    const size_t off = (size_t)u * D_EMB;
    #pragma unroll
    for (int i = 0; i < 4; i++) {
        int d = lane * 4 + i * 128;
        *reinterpret_cast<uint2*>(&g_E[off + d]) = pack_bf16x4(ev[i], inv_e);
    }
}

// ---------------- async chunk load into 128B-row XOR-swizzled smem ----------
__device__ __forceinline__ void load_chunk_async(uint32_t As, uint32_t Bs,
                                                 int m_base, int n_base,
                                                 int c, int tid) {
    const int kof = c * KC;
    #pragma unroll
    for (int i = 0; i < 4; i++) {
        int g = tid + i * 256;
        int row = g >> 3, j = g & 7;
        const char* src = reinterpret_cast<const char*>(
            g_E + (size_t)(m_base + row) * D_EMB + kof) + j * 16;
        uint32_t dst = As + row * 128 + ((j * 16) ^ ((row & 7) * 16));
        cp16(dst, src);
    }
    #pragma unroll
    for (int i = 0; i < 4; i++) {
        int g = tid + i * 256;
        int row = g >> 3, j = g & 7;
        const char* src = reinterpret_cast<const char*>(
            g_C + (size_t)(n_base + row) * D_EMB + kof) + j * 16;
        uint32_t dst = Bs + row * 128 + ((j * 16) ^ ((row & 7) * 16));
        cp16(dst, src);
    }
}

// ============================================================================
// Kernel 2: mma.sync bf16 GEMM (128x128, K=512), 3-stage cp.async ring,
// 8 warps (32x64 warp tiles), ONE barrier per chunk, fused exp-sum epilogue.
// grid = (MTILES, NTILES), block = 256 (warp_m = wid&3, warp_n = wid>>2)
// ============================================================================
__global__ void __launch_bounds__(256, 2) gemm_kernel(const float* __restrict__ wp,
                                                      const float* __restrict__ bp) {
    extern __shared__ char dsm[];
    const uint32_t sb = smem_u32(dsm);
    const uint32_t aAddr[3] = { sb,               sb + STAGE_BYTES,
                                sb + 2 * STAGE_BYTES };
    const uint32_t bAddr[3] = { sb + 16384,       sb + STAGE_BYTES + 16384,
                                sb + 2 * STAGE_BYTES + 16384 };

    const int tid  = threadIdx.x;
    const int wid  = tid >> 5;
    const int lane = tid & 31;
    const int warp_m = wid & 3;
    const int warp_n = wid >> 2;
    const int m_base = blockIdx.x * BM;
    const int n_base = blockIdx.y * BN;

    float acc[2][8][4];
    #pragma unroll
    for (int mi = 0; mi < 2; mi++)
        #pragma unroll
        for (int ni = 0; ni < 8; ni++)
            #pragma unroll
            for (int k = 0; k < 4; k++) acc[mi][ni][k] = 0.f;

    const int rowA0 = warp_m * 32 + (lane & 15);
    const int gA    = lane >> 4;
    const int rowB0 = warp_n * 64 + (lane & 7) + (((lane >> 4) & 1) << 3);
    const int gBsel = (lane >> 3) & 1;

    load_chunk_async(aAddr[0], bAddr[0], m_base, n_base, 0, tid);
    CP_COMMIT();
    load_chunk_async(aAddr[1], bAddr[1], m_base, n_base, 1, tid);
    CP_COMMIT();

    #pragma unroll
    for (int c = 0; c < NCH; c++) {
        if (c + 1 < NCH) { CP_WAIT(1); } else { CP_WAIT(0); }
        __syncthreads();
        if (c + 2 < NCH) {
            const int s = (c + 2) % 3;
            load_chunk_async(aAddr[s], bAddr[s], m_base, n_base, c + 2, tid);
            CP_COMMIT();
        }
        const uint32_t As = aAddr[c % 3], Bs = bAddr[c % 3];
        #pragma unroll
        for (int ks = 0; ks < 4; ks++) {
            uint32_t a[2][4];
            #pragma unroll
            for (int mi = 0; mi < 2; mi++) {
                int rowA = rowA0 + mi * 16;
                uint32_t addr = As + rowA * 128 +
                                (((ks * 2 + gA) * 16) ^ ((rowA & 7) * 16));
                LDSM_X4(a[mi][0], a[mi][1], a[mi][2], a[mi][3], addr);
            }
            #pragma unroll
            for (int p = 0; p < 4; p++) {
                int rowB = rowB0 + p * 16;
                int gB = ks * 2 + gBsel;
                uint32_t addr = Bs + rowB * 128 + ((gB * 16) ^ ((rowB & 7) * 16));
                uint32_t b0, b1, b2, b3;
                LDSM_X4(b0, b1, b2, b3, addr);
                mma16816(acc[0][2 * p],     a[0], b0, b1);
                mma16816(acc[0][2 * p + 1], a[0], b2, b3);
                mma16816(acc[1][2 * p],     a[1], b0, b1);
                mma16816(acc[1][2 * p + 1], a[1], b2, b3);
            }
        }
        // no trailing barrier: 3-stage ring makes it redundant.
    }

    // ---- fused epilogue: exp-sum per row, leave-one-out replacement ----
    const float wv  = *wp;
    const float bpr = fmaf(wv, SIM_EPS, *bp);
    const int l4 = lane >> 2, lm = lane & 3;
    const int colbase = n_base + warp_n * 64 + 2 * lm;
    const int part = blockIdx.y * 2 + warp_n;

    #pragma unroll
    for (int mi = 0; mi < 2; mi++) {
        #pragma unroll
        for (int h = 0; h < 2; h++) {
            const int rg = m_base + warp_m * 32 + mi * 16 + h * 8 + l4;
            const int spk = rg / N_UTT;
            const float dval = g_diag[rg];
            float s = 0.f;
            #pragma unroll
            for (int ni = 0; ni < 8; ni++) {
                #pragma unroll
                for (int cc = 0; cc < 2; cc++) {
                    float cv = acc[mi][ni][2 * h + cc];
                    int col = colbase + ni * 8 + cc;
                    if (col == spk) cv = dval;
                    s += __expf(fmaf(wv, cv, bpr));
                }
            }
            s += __shfl_xor_sync(0xFFFFFFFFu, s, 1);
            s += __shfl_xor_sync(0xFFFFFFFFu, s, 2);
            if (lm == 0) g_rowsum[part][rg] = s;
        }
    }
}

// ============================================================================
// Kernel 3 (fused): per-row LSE - pos, block partials, last block reduces.
// grid = FIN_BLOCKS x 512. g_fin self-resets for graph replay.
// ============================================================================
__global__ void __launch_bounds__(512) finalize_kernel(const float* __restrict__ wp,
                                                       const float* __restrict__ bp,
                                                       float* __restrict__ out) {
    __shared__ float sRed[16];
    __shared__ bool sLast;
    const int tid = threadIdx.x;
    const int r = blockIdx.x * 512 + tid;
    const float wv = *wp, bv = *bp;
    float s = 0.f;
    #pragma unroll
    for (int p = 0; p < NPART; p++) s += g_rowsum[p][r];
    float acc = logf(s + SIM_EPS) - fmaf(wv, g_diag[r] + SIM_EPS, bv);
    #pragma unroll
    for (int o = 16; o > 0; o >>= 1) acc += __shfl_down_sync(0xFFFFFFFFu, acc, o);
    if ((tid & 31) == 0) sRed[tid >> 5] = acc;
    __syncthreads();
    if (tid < 32) {
        float v = (tid < 16) ? sRed[tid] : 0.f;
        #pragma unroll
        for (int o = 8; o > 0; o >>= 1) v += __shfl_down_sync(0xFFFFFFFFu, v, o);
        if (tid == 0) {
            g_bsum[blockIdx.x] = v;
            __threadfence();
            unsigned int t = atomicAdd(&g_fin, 1u);
            sLast = (t == FIN_BLOCKS - 1);
        }
    }
    __syncthreads();
    if (sLast && tid < 32) {
        __threadfence();
        volatile float* vb = g_bsum;
        float v = vb[tid] + ((tid < FIN_BLOCKS - 32) ? vb[tid + 32] : 0.f);
        #pragma unroll
        for (int o = 16; o > 0; o >>= 1) v += __shfl_down_sync(0xFFFFFFFFu, v, o);
        if (tid == 0) {
            out[0] = v;
            g_fin = 0;      // reset ticket for next graph replay
        }
    }
}

// ============================================================================
extern "C" void kernel_launch(void* const* d_in, const int* in_sizes, int n_in,
                              void* d_out, int out_size) {
    const float* emb = (const float*)d_in[0];
    const float* w   = (const float*)d_in[1];
    const float* b   = (const float*)d_in[2];
    float* out = (float*)d_out;

    cudaFuncSetAttribute(gemm_kernel,
                         cudaFuncAttributeMaxDynamicSharedMemorySize, SMEM_DYN);

    sum_kernel<<<N_SPK, 256>>>(emb);
    norm_kernel<<<R_TOT / 8, 256>>>(emb);
    gemm_kernel<<<dim3(MTILES, NTILES), 256, SMEM_DYN>>>(w, b);
    finalize_kernel<<<FIN_BLOCKS, 512>>>(w, b, out);
}

// round 17
// speedup vs baseline: 1.0301x; 1.0301x over previous
#include <cuda_runtime.h>
#include <cuda_bf16.h>
#include <cstdint>

// ---------------- problem constants ----------------
static constexpr int N_SPK = 1024;
static constexpr int N_UTT = 20;
static constexpr int D_EMB = 512;
static constexpr int R_TOT = N_SPK * N_UTT;   // 20480 rows

static constexpr float COS_EPS = 1e-8f;
static constexpr float SIM_EPS = 1e-6f;

// ---------------- GEMM tiling (R8/R15 proven config) ----------------
static constexpr int BM  = 128;               // rows per CTA
static constexpr int BN  = 128;               // centroid cols per CTA
static constexpr int KC  = 64;                // K chunk (bf16) -> 128B rows in smem
static constexpr int NCH = D_EMB / KC;        // 8 chunks
static constexpr int MTILES = R_TOT / BM;     // 160
static constexpr int NTILES = N_SPK / BN;     // 8
static constexpr int NPART  = NTILES * 2;     // 16 row-sum partial arrays
static constexpr int FIN_BLOCKS = 80;         // finalize blocks (256 rows each)

// 3-stage ring: [A_s 16K | B_s 16K] x 3
static constexpr int STAGE_BYTES = 2 * BM * KC * 2;     // 32768
static constexpr int SMEM_DYN = 3 * STAGE_BYTES;        // 98304

// ---------------- scratch (device globals; no allocs allowed) ----------------
__device__ __nv_bfloat16 g_E[R_TOT * D_EMB];      // normalized embeddings (bf16)
__device__ __nv_bfloat16 g_C[N_SPK * D_EMB];      // normalized centroids (bf16)
__device__ float         g_diag[R_TOT];           // leave-one-out cosine (fp32)
__device__ float         g_rowsum[NPART][R_TOT];  // partial exp sums
__device__ float         g_bsum[FIN_BLOCKS];      // finalize partials
__device__ unsigned int  g_fin;                   // finalize ticket (self-resetting)

// ---------------- PTX helpers (plain-sm_103-safe) ----------------
__device__ __forceinline__ uint32_t smem_u32(const void* p) {
    uint32_t a;
    asm("{ .reg .u64 t; cvta.to.shared.u64 t, %1; cvt.u32.u64 %0, t; }"
        : "=r"(a) : "l"(p));
    return a;
}
__device__ __forceinline__ void cp16(uint32_t dst, const void* src) {
    asm volatile("cp.async.cg.shared.global [%0], [%1], 16;"
                 :: "r"(dst), "l"(src));
}
#define CP_COMMIT() asm volatile("cp.async.commit_group;" ::: "memory")
#define CP_WAIT(n)  asm volatile("cp.async.wait_group %0;" :: "n"(n) : "memory")

#define LDSM_X4(r0, r1, r2, r3, addr)                                          \
    asm volatile("ldmatrix.sync.aligned.m8n8.x4.shared.b16 {%0,%1,%2,%3}, [%4];" \
                 : "=r"(r0), "=r"(r1), "=r"(r2), "=r"(r3) : "r"(addr))

__device__ __forceinline__ void mma16816(float* c, const uint32_t* a,
                                         uint32_t b0, uint32_t b1) {
    asm volatile(
        "mma.sync.aligned.m16n8k16.row.col.f32.bf16.bf16.f32 "
        "{%0,%1,%2,%3}, {%4,%5,%6,%7}, {%8,%9}, {%0,%1,%2,%3};"
        : "+f"(c[0]), "+f"(c[1]), "+f"(c[2]), "+f"(c[3])
        : "r"(a[0]), "r"(a[1]), "r"(a[2]), "r"(a[3]), "r"(b0), "r"(b1));
}

// pack 4 floats (scaled) into 4 bf16 = uint2
__device__ __forceinline__ uint2 pack_bf16x4(float4 v, float scale) {
    __nv_bfloat162 lo, hi;
    lo.x = __float2bfloat16(v.x * scale);
    lo.y = __float2bfloat16(v.y * scale);
    hi.x = __float2bfloat16(v.z * scale);
    hi.y = __float2bfloat16(v.w * scale);
    uint2 pk;
    pk.x = *reinterpret_cast<uint32_t*>(&lo);
    pk.y = *reinterpret_cast<uint32_t*>(&hi);
    return pk;
}

// ============================================================================
// Kernel 1: per-speaker prep (R15 proven), 352 threads, <=2 items per warp.
// ============================================================================
__device__ __forceinline__ void utt_partials(const float* __restrict__ erow,
                                             const float* __restrict__ sSum,
                                             int lane, float4* ev,
                                             float& ee, float& se) {
    ee = 0.f; se = 0.f;
    #pragma unroll
    for (int i = 0; i < 4; i++) {
        int d = lane * 4 + i * 128;
        ev[i] = *reinterpret_cast<const float4*>(erow + d);
        float4 S4 = *reinterpret_cast<const float4*>(&sSum[d]);
        ee += ev[i].x * ev[i].x + ev[i].y * ev[i].y +
              ev[i].z * ev[i].z + ev[i].w * ev[i].w;
        se += ev[i].x * S4.x + ev[i].y * S4.y +
              ev[i].z * S4.z + ev[i].w * S4.w;
    }
}

__device__ __forceinline__ void utt_finish(int n, int item, int lane,
                                           const float4* ev, float ee, float se,
                                           float SS, float invM1) {
    float ec = (se - ee) * invM1;
    float cc = (SS - 2.f * se + ee) * invM1 * invM1;
    float inv_e = 1.0f / fmaxf(sqrtf(ee), COS_EPS);
    float inv_c = 1.0f / fmaxf(sqrtf(cc), COS_EPS);
    if (lane == 0) g_diag[n * N_UTT + item] = ec * inv_e * inv_c;
    const size_t off = (size_t)(n * N_UTT + item) * D_EMB;
    #pragma unroll
    for (int i = 0; i < 4; i++) {
        int d = lane * 4 + i * 128;
        *reinterpret_cast<uint2*>(&g_E[off + d]) = pack_bf16x4(ev[i], inv_e);
    }
}

__global__ void __launch_bounds__(352) prep_kernel(const float* __restrict__ emb) {
    __shared__ float sSum[D_EMB];   // 2 KB
    __shared__ float sRed[8];
    __shared__ float sCS;
    __shared__ float sSS;

    const int n    = blockIdx.x;
    const int tid  = threadIdx.x;
    const int wid  = tid >> 5;
    const int lane = tid & 31;
    const float* spk = emb + (size_t)n * N_UTT * D_EMB;

    if (tid < 256) {
        float2 s = {0.f, 0.f};
        #pragma unroll
        for (int m = 0; m < N_UTT; m++) {
            float2 v = *reinterpret_cast<const float2*>(spk + m * D_EMB + 2 * tid);
            s.x += v.x; s.y += v.y;
        }
        *reinterpret_cast<float2*>(&sSum[2 * tid]) = s;
        float ssp = s.x * s.x + s.y * s.y;
        #pragma unroll
        for (int o = 16; o > 0; o >>= 1)
            ssp += __shfl_xor_sync(0xFFFFFFFFu, ssp, o);
        if (lane == 0) sRed[wid] = ssp;
    }
    __syncthreads();
    if (tid == 0) {
        float SS = 0.f;
        #pragma unroll
        for (int w = 0; w < 8; w++) SS += sRed[w];
        sSS = SS;
        float cnorm = sqrtf(SS) * (1.0f / N_UTT);
        sCS = 1.0f / (N_UTT * fmaxf(cnorm, COS_EPS));
    }
    __syncthreads();
    const float SS = sSS;
    const float invM1 = 1.0f / (N_UTT - 1);

    if (wid <= 8) {
        const int a = wid, b = wid + 11;
        float4 eva[4], evb[4];
        float eea, sea, eeb, seb;
        utt_partials(spk + a * D_EMB, sSum, lane, eva, eea, sea);
        utt_partials(spk + b * D_EMB, sSum, lane, evb, eeb, seb);
        #pragma unroll
        for (int o = 16; o > 0; o >>= 1) {
            eea += __shfl_xor_sync(0xFFFFFFFFu, eea, o);
            sea += __shfl_xor_sync(0xFFFFFFFFu, sea, o);
            eeb += __shfl_xor_sync(0xFFFFFFFFu, eeb, o);
            seb += __shfl_xor_sync(0xFFFFFFFFu, seb, o);
        }
        utt_finish(n, a, lane, eva, eea, sea, SS, invM1);
        utt_finish(n, b, lane, evb, eeb, seb, SS, invM1);
    } else if (wid == 9) {
        float4 ev[4]; float ee, se;
        utt_partials(spk + 9 * D_EMB, sSum, lane, ev, ee, se);
        #pragma unroll
        for (int o = 16; o > 0; o >>= 1) {
            ee += __shfl_xor_sync(0xFFFFFFFFu, ee, o);
            se += __shfl_xor_sync(0xFFFFFFFFu, se, o);
        }
        utt_finish(n, 9, lane, ev, ee, se, SS, invM1);
        const float cs = sCS;
        #pragma unroll
        for (int i = 0; i < 4; i++) {
            int d = lane * 4 + i * 128;
            float4 v = *reinterpret_cast<const float4*>(&sSum[d]);
            *reinterpret_cast<uint2*>(&g_C[(size_t)n * D_EMB + d]) =
                pack_bf16x4(v, cs);
        }
    } else {  // wid == 10
        float4 ev[4]; float ee, se;
        utt_partials(spk + 10 * D_EMB, sSum, lane, ev, ee, se);
        #pragma unroll
        for (int o = 16; o > 0; o >>= 1) {
            ee += __shfl_xor_sync(0xFFFFFFFFu, ee, o);
            se += __shfl_xor_sync(0xFFFFFFFFu, se, o);
        }
        utt_finish(n, 10, lane, ev, ee, se, SS, invM1);
    }
}

// ---------------- async chunk load into 128B-row XOR-swizzled smem ----------
__device__ __forceinline__ void load_chunk_async(uint32_t As, uint32_t Bs,
                                                 int m_base, int n_base,
                                                 int c, int tid) {
    const int kof = c * KC;
    #pragma unroll
    for (int i = 0; i < 4; i++) {
        int g = tid + i * 256;
        int row = g >> 3, j = g & 7;
        const char* src = reinterpret_cast<const char*>(
            g_E + (size_t)(m_base + row) * D_EMB + kof) + j * 16;
        uint32_t dst = As + row * 128 + ((j * 16) ^ ((row & 7) * 16));
        cp16(dst, src);
    }
    #pragma unroll
    for (int i = 0; i < 4; i++) {
        int g = tid + i * 256;
        int row = g >> 3, j = g & 7;
        const char* src = reinterpret_cast<const char*>(
            g_C + (size_t)(n_base + row) * D_EMB + kof) + j * 16;
        uint32_t dst = Bs + row * 128 + ((j * 16) ^ ((row & 7) * 16));
        cp16(dst, src);
    }
}

// ============================================================================
// Kernel 2: mma.sync bf16 GEMM (128x128, K=512), 3-stage cp.async ring,
// 8 warps (32x64 warp tiles), ONE barrier per chunk, fused exp-sum epilogue.
// grid = (MTILES, NTILES), block = 256 (warp_m = wid&3, warp_n = wid>>2)
// ============================================================================
__global__ void __launch_bounds__(256, 2) gemm_kernel(const float* __restrict__ wp,
                                                      const float* __restrict__ bp) {
    extern __shared__ char dsm[];
    const uint32_t sb = smem_u32(dsm);
    const uint32_t aAddr[3] = { sb,               sb + STAGE_BYTES,
                                sb + 2 * STAGE_BYTES };
    const uint32_t bAddr[3] = { sb + 16384,       sb + STAGE_BYTES + 16384,
                                sb + 2 * STAGE_BYTES + 16384 };

    const int tid  = threadIdx.x;
    const int wid  = tid >> 5;
    const int lane = tid & 31;
    const int warp_m = wid & 3;
    const int warp_n = wid >> 2;
    const int m_base = blockIdx.x * BM;
    const int n_base = blockIdx.y * BN;

    float acc[2][8][4];
    #pragma unroll
    for (int mi = 0; mi < 2; mi++)
        #pragma unroll
        for (int ni = 0; ni < 8; ni++)
            #pragma unroll
            for (int k = 0; k < 4; k++) acc[mi][ni][k] = 0.f;

    const int rowA0 = warp_m * 32 + (lane & 15);
    const int gA    = lane >> 4;
    const int rowB0 = warp_n * 64 + (lane & 7) + (((lane >> 4) & 1) << 3);
    const int gBsel = (lane >> 3) & 1;

    load_chunk_async(aAddr[0], bAddr[0], m_base, n_base, 0, tid);
    CP_COMMIT();
    load_chunk_async(aAddr[1], bAddr[1], m_base, n_base, 1, tid);
    CP_COMMIT();

    #pragma unroll
    for (int c = 0; c < NCH; c++) {
        if (c + 1 < NCH) { CP_WAIT(1); } else { CP_WAIT(0); }
        __syncthreads();
        if (c + 2 < NCH) {
            const int s = (c + 2) % 3;
            load_chunk_async(aAddr[s], bAddr[s], m_base, n_base, c + 2, tid);
            CP_COMMIT();
        }
        const uint32_t As = aAddr[c % 3], Bs = bAddr[c % 3];
        #pragma unroll
        for (int ks = 0; ks < 4; ks++) {
            uint32_t a[2][4];
            #pragma unroll
            for (int mi = 0; mi < 2; mi++) {
                int rowA = rowA0 + mi * 16;
                uint32_t addr = As + rowA * 128 +
                                (((ks * 2 + gA) * 16) ^ ((rowA & 7) * 16));
                LDSM_X4(a[mi][0], a[mi][1], a[mi][2], a[mi][3], addr);
            }
            #pragma unroll
            for (int p = 0; p < 4; p++) {
                int rowB = rowB0 + p * 16;
                int gB = ks * 2 + gBsel;
                uint32_t addr = Bs + rowB * 128 + ((gB * 16) ^ ((rowB & 7) * 16));
                uint32_t b0, b1, b2, b3;
                LDSM_X4(b0, b1, b2, b3, addr);
                mma16816(acc[0][2 * p],     a[0], b0, b1);
                mma16816(acc[0][2 * p + 1], a[0], b2, b3);
                mma16816(acc[1][2 * p],     a[1], b0, b1);
                mma16816(acc[1][2 * p + 1], a[1], b2, b3);
            }
        }
        // no trailing barrier: 3-stage ring makes it redundant.
    }

    // ---- fused epilogue: exp-sum per row, leave-one-out replacement ----
    const float wv  = *wp;
    const float bpr = fmaf(wv, SIM_EPS, *bp);
    const int l4 = lane >> 2, lm = lane & 3;
    const int colbase = n_base + warp_n * 64 + 2 * lm;
    const int part = blockIdx.y * 2 + warp_n;

    #pragma unroll
    for (int mi = 0; mi < 2; mi++) {
        #pragma unroll
        for (int h = 0; h < 2; h++) {
            const int rg = m_base + warp_m * 32 + mi * 16 + h * 8 + l4;
            const int spk = rg / N_UTT;
            const float dval = g_diag[rg];
            float s = 0.f;
            #pragma unroll
            for (int ni = 0; ni < 8; ni++) {
                #pragma unroll
                for (int cc = 0; cc < 2; cc++) {
                    float cv = acc[mi][ni][2 * h + cc];
                    int col = colbase + ni * 8 + cc;
                    if (col == spk) cv = dval;
                    s += __expf(fmaf(wv, cv, bpr));
                }
            }
            s += __shfl_xor_sync(0xFFFFFFFFu, s, 1);
            s += __shfl_xor_sync(0xFFFFFFFFu, s, 2);
            if (lm == 0) g_rowsum[part][rg] = s;
        }
    }
}

// ============================================================================
// Kernel 3 (fused, 4-way parallel): grid = 80 x 1024.
// Each block: 256 rows; each row's 16-partial sum split over 4 threads
// (q = tid>>8 handles partials 4q..4q+3), combined via smem; q==0 quarter
// does log/pos + block reduce. Ticket: last block reduces 80 partials.
// ============================================================================
__global__ void __launch_bounds__(1024) finalize_kernel(const float* __restrict__ wp,
                                                        const float* __restrict__ bp,
                                                        float* __restrict__ out) {
    __shared__ float sQ[1024];
    __shared__ float sRed[8];
    __shared__ bool sLast;
    const int tid  = threadIdx.x;
    const int q    = tid >> 8;
    const int rloc = tid & 255;
    const int r    = blockIdx.x * 256 + rloc;

    float sq = 0.f;
    #pragma unroll
    for (int p = 0; p < 4; p++) sq += g_rowsum[4 * q + p][r];
    sQ[tid] = sq;
    __syncthreads();

    if (q == 0) {
        const float wv = *wp, bv = *bp;
        float s = sQ[rloc] + sQ[256 + rloc] + sQ[512 + rloc] + sQ[768 + rloc];
        float acc = logf(s + SIM_EPS) - fmaf(wv, g_diag[r] + SIM_EPS, bv);
        #pragma unroll
        for (int o = 16; o > 0; o >>= 1)
            acc += __shfl_down_sync(0xFFFFFFFFu, acc, o);
        if ((rloc & 31) == 0) sRed[rloc >> 5] = acc;
    }
    __syncthreads();
    if (tid == 0) {
        float v = 0.f;
        #pragma unroll
        for (int w = 0; w < 8; w++) v += sRed[w];
        g_bsum[blockIdx.x] = v;
        __threadfence();
        unsigned int t = atomicAdd(&g_fin, 1u);
        sLast = (t == FIN_BLOCKS - 1);
    }
    __syncthreads();
    if (sLast && tid < 32) {
        __threadfence();
        volatile float* vb = g_bsum;
        float v = vb[tid];
        if (tid + 32 < FIN_BLOCKS) v += vb[tid + 32];
        if (tid + 64 < FIN_BLOCKS) v += vb[tid + 64];
        #pragma unroll
        for (int o = 16; o > 0; o >>= 1)
            v += __shfl_down_sync(0xFFFFFFFFu, v, o);
        if (tid == 0) {
            out[0] = v;
            g_fin = 0;      // reset ticket for next graph replay
        }
    }
}

// ============================================================================
extern "C" void kernel_launch(void* const* d_in, const int* in_sizes, int n_in,
                              void* d_out, int out_size) {
    const float* emb = (const float*)d_in[0];
    const float* w   = (const float*)d_in[1];
    const float* b   = (const float*)d_in[2];
    float* out = (float*)d_out;

    cudaFuncSetAttribute(gemm_kernel,
                         cudaFuncAttributeMaxDynamicSharedMemorySize, SMEM_DYN);

    prep_kernel<<<N_SPK, 352>>>(emb);
    gemm_kernel<<<dim3(MTILES, NTILES), 256, SMEM_DYN>>>(w, b);
    finalize_kernel<<<FIN_BLOCKS, 1024>>>(w, b, out);
}